// round 15
// baseline (speedup 1.0000x reference)
#include <cuda_runtime.h>

// SSIM loss — R5 compute verbatim, SINGLE kernel.
// All blocks except the LAST exit via fire-and-forget REDs (relaxed f32 sum +
// release u32 counter). The LAST block (bid = NBLK-1) is the finisher: the
// scheduler cannot start it until the grid has nearly drained (it sits in the
// final wave), so its acquire-spin is sub-microsecond — unlike R14, where
// block 0 was the finisher and spun for the whole kernel (+4us).

#define NT      256
#define EXTX    64
#define TILE_X  54
#define TILE_Y  48
#define R       12
#define SVS     65          // row stride in 16B elements (odd -> conflict-free)
#define IMG     512
#define GRIDX   10
#define GRIDY   11
#define GRIDZ   48
#define NBLK    (GRIDX * GRIDY * GRIDZ)

#define KWc0 0.0010283801f
#define KWc1 0.0075987582f
#define KWc2 0.0360007696f
#define KWc3 0.1093606947f
#define KWc4 0.2130055430f
#define KWc5 0.2660117300f

#define C1V 0.0001f
#define C2V 0.0009f

__device__ float    g_sum = 0.0f;
__device__ unsigned g_cnt = 0u;

__device__ __forceinline__ void fma2(float2& d, float2 a, float2 b) {
    asm("fma.rn.f32x2 %0, %1, %2, %0;"
        : "+l"(reinterpret_cast<unsigned long long&>(d))
        : "l"(reinterpret_cast<const unsigned long long&>(a)),
          "l"(reinterpret_cast<const unsigned long long&>(b)));
}

__global__ void __launch_bounds__(NT, 3)
ssim_lastblk_kernel(const float* __restrict__ img1,
                    const float* __restrict__ img2,
                    float* __restrict__ out)
{
    float2 wpair[6];
    wpair[0] = make_float2(KWc0, KWc0); wpair[1] = make_float2(KWc1, KWc1);
    wpair[2] = make_float2(KWc2, KWc2); wpair[3] = make_float2(KWc3, KWc3);
    wpair[4] = make_float2(KWc4, KWc4); wpair[5] = make_float2(KWc5, KWc5);
    #define WPK(k) wpair[(k) <= 5 ? (k) : 10 - (k)]

    extern __shared__ float4 sV[];   // [TILE_Y][SVS] : (A,B,P,Q) vertical-filtered

    const int tid  = threadIdx.x;
    const int base = blockIdx.z * (IMG * IMG);
    const int x0   = blockIdx.x * TILE_X;
    const int y0   = blockIdx.y * TILE_Y;

    const bool interior = (x0 >= 5) && (x0 + EXTX - 5 <= IMG) &&
                          (y0 >= 5) && (y0 + TILE_Y + 5 <= IMG);

    // ---------------- Stage V: vertical 11-tap, f32x2 registers ------------
    {
        const int c   = tid & (EXTX - 1);
        const int g   = tid >> 6;            // row group 0..3
        const int gx  = x0 - 5 + c;
        const int iy0 = y0 + g * R - 5;

        float2 accAB[R], accPQ[R];
        #pragma unroll
        for (int o = 0; o < R; ++o) {
            accAB[o] = make_float2(0.f, 0.f);
            accPQ[o] = make_float2(0.f, 0.f);
        }

        if (interior) {
            const float* p1 = img1 + base + iy0 * IMG + gx;
            const float* p2 = img2 + base + iy0 * IMG + gx;
            #pragma unroll
            for (int j = 0; j < R + 10; ++j) {
                float a = __ldg(p1 + j * IMG);
                float b = __ldg(p2 + j * IMG);
                float2 ab = make_float2(a, b);
                float2 pq = make_float2(a * a + b * b, a * b);
                #pragma unroll
                for (int o = 0; o < R; ++o) {
                    int k = j - o;
                    if (k >= 0 && k <= 10) {
                        fma2(accAB[o], WPK(k), ab);
                        fma2(accPQ[o], WPK(k), pq);
                    }
                }
            }
        } else {
            const bool xok = (unsigned)gx < (unsigned)IMG;
            #pragma unroll
            for (int j = 0; j < R + 10; ++j) {
                int gy = iy0 + j;
                float a = 0.f, b = 0.f;
                if (xok && (unsigned)gy < (unsigned)IMG) {
                    int off = base + gy * IMG + gx;
                    a = __ldg(img1 + off);
                    b = __ldg(img2 + off);
                }
                float2 ab = make_float2(a, b);
                float2 pq = make_float2(a * a + b * b, a * b);
                #pragma unroll
                for (int o = 0; o < R; ++o) {
                    int k = j - o;
                    if (k >= 0 && k <= 10) {
                        fma2(accAB[o], WPK(k), ab);
                        fma2(accPQ[o], WPK(k), pq);
                    }
                }
            }
        }

        #pragma unroll
        for (int o = 0; o < R; ++o)
            sV[(g * R + o) * SVS + c] =
                make_float4(accAB[o].x, accAB[o].y, accPQ[o].x, accPQ[o].y);
    }
    __syncthreads();

    // ------- Stage H: j-streaming horizontal 11-tap + SSIM, 6 cols/task ----
    float loss = 0.0f;
    for (int t = tid; t < 9 * TILE_Y; t += NT) {     // 9 chunks x 48 rows = 432
        int row = t % TILE_Y;
        int c0  = (t / TILE_Y) * 6;

        float2 oAB[6], oPQ[6];
        #pragma unroll
        for (int cc = 0; cc < 6; ++cc) {
            oAB[cc] = make_float2(0.f, 0.f);
            oPQ[cc] = make_float2(0.f, 0.f);
        }

        #pragma unroll
        for (int j = 0; j < 16; ++j) {
            float4 v = sV[row * SVS + c0 + j];
            float2 vab = make_float2(v.x, v.y);
            float2 vpq = make_float2(v.z, v.w);
            #pragma unroll
            for (int cc = 0; cc < 6; ++cc) {
                int k = j - cc;
                if (k >= 0 && k <= 10) {
                    fma2(oAB[cc], WPK(k), vab);
                    fma2(oPQ[cc], WPK(k), vpq);
                }
            }
        }

        int  gy  = y0 + row;
        int  ox0 = x0 + c0;
        bool yok = gy < IMG;

        #pragma unroll
        for (int cc = 0; cc < 6; ++cc) {
            float A = oAB[cc].x, B = oAB[cc].y;
            float P = oPQ[cc].x, Q = oPQ[cc].y;
            float AB   = A * B;
            float AA   = A * A;
            float num1 = 2.0f * AB + C1V;
            float num2 = 2.0f * (Q - AB) + C2V;
            float den1 = fmaf(B, B, C1V) + AA;           // AA+BB+C1
            float den2 = (P - den1) + (C1V + C2V);       // P-AA-BB+C2
            float ssim = __fdividef(num1 * num2, den1 * den2);
            float l    = fmaf(ssim, -0.5f, 0.5f);        // (1-ssim)/2
            l = fminf(fmaxf(l, 0.0f), 0.5f);             // clip (NaN-safe)
            if (yok && (ox0 + cc) < IMG) loss += l;
        }
    }

    // ------------- Block reduction -----------------------------------------
    #pragma unroll
    for (int s = 16; s > 0; s >>= 1)
        loss += __shfl_xor_sync(0xFFFFFFFFu, loss, s);

    __shared__ float warpsum[NT / 32];
    if ((tid & 31) == 0) warpsum[tid >> 5] = loss;
    __syncthreads();

    const bool is_finisher = (blockIdx.x == GRIDX - 1) &&
                             (blockIdx.y == GRIDY - 1) &&
                             (blockIdx.z == GRIDZ - 1);   // scheduled last

    if (tid == 0) {
        float bsum = 0.f;
        #pragma unroll
        for (int w = 0; w < NT / 32; ++w) bsum += warpsum[w];

        if (!is_finisher) {
            // fire-and-forget: relaxed sum, then RELEASE counter increment
            asm volatile("red.relaxed.gpu.global.add.f32 [%0], %1;"
                         :: "l"(&g_sum), "f"(bsum) : "memory");
            asm volatile("red.release.gpu.global.add.u32 [%0], %1;"
                         :: "l"(&g_cnt), "r"(1u) : "memory");
        } else {
            // finisher: started in the final wave; short drain only
            unsigned c;
            do {
                asm volatile("ld.acquire.gpu.global.u32 %0, [%1];"
                             : "=r"(c) : "l"(&g_cnt) : "memory");
                if (c != NBLK - 1) __nanosleep(64);
            } while (c != NBLK - 1);

            float s;
            asm volatile("ld.relaxed.gpu.global.f32 %0, [%1];"
                         : "=f"(s) : "l"(&g_sum) : "memory");
            const float inv_total = 1.0f / (16.0f * 3.0f * 512.0f * 512.0f);
            out[0] = (s + bsum) * inv_total;

            // reset for next graph replay (replays are stream-serialized)
            asm volatile("st.relaxed.gpu.global.f32 [%0], %1;"
                         :: "l"(&g_sum), "f"(0.0f) : "memory");
            asm volatile("st.relaxed.gpu.global.u32 [%0], %1;"
                         :: "l"(&g_cnt), "r"(0u) : "memory");
        }
    }
}

extern "C" void kernel_launch(void* const* d_in, const int* in_sizes, int n_in,
                              void* d_out, int out_size)
{
    const float* img1 = (const float*)d_in[0];
    const float* img2 = (const float*)d_in[1];
    float* out = (float*)d_out;

    const int smem_bytes = TILE_Y * SVS * (int)sizeof(float4);  // 49920
    cudaFuncSetAttribute(ssim_lastblk_kernel,
                         cudaFuncAttributeMaxDynamicSharedMemorySize, smem_bytes);

    dim3 grid(GRIDX, GRIDY, GRIDZ);   // 10 x 11 x 48 = 5280 blocks
    ssim_lastblk_kernel<<<grid, NT, smem_bytes>>>(img1, img2, out);
}

// round 16
// speedup vs baseline: 1.0689x; 1.0689x over previous
#include <cuda_runtime.h>

// SSIM loss — R5/R13 compute verbatim, SINGLE kernel, ZERO ordering ops.
// Protocol: one 64-bit packed relaxed RED per block:
//   bits 48..63 = block count (+1 each), bits 0..47 = fixed-point(2^20) loss sum.
// Atomicity of the single word replaces release/acquire entirely (R11/12/14/15
// showed any release/fence/returning-atomic tail costs +4-5.5us).
// Finisher = last-scheduled block; the same volatile load that sees
// count==NBLK already carries the final sum.

#define NT      256
#define EXTX    64
#define TILE_X  54
#define TILE_Y  48
#define R       12
#define SVS     65          // row stride in 16B elements (odd -> conflict-free)
#define IMG     512
#define GRIDX   10
#define GRIDY   11
#define GRIDZ   48
#define NBLK    (GRIDX * GRIDY * GRIDZ)

#define KWc0 0.0010283801f
#define KWc1 0.0075987582f
#define KWc2 0.0360007696f
#define KWc3 0.1093606947f
#define KWc4 0.2130055430f
#define KWc5 0.2660117300f

#define C1V 0.0001f
#define C2V 0.0009f

__device__ unsigned long long g_pack = 0ull;

__device__ __forceinline__ void fma2(float2& d, float2 a, float2 b) {
    asm("fma.rn.f32x2 %0, %1, %2, %0;"
        : "+l"(reinterpret_cast<unsigned long long&>(d))
        : "l"(reinterpret_cast<const unsigned long long&>(a)),
          "l"(reinterpret_cast<const unsigned long long&>(b)));
}

__global__ void __launch_bounds__(NT, 3)
ssim_pack_kernel(const float* __restrict__ img1,
                 const float* __restrict__ img2,
                 float* __restrict__ out)
{
    float2 wpair[6];
    wpair[0] = make_float2(KWc0, KWc0); wpair[1] = make_float2(KWc1, KWc1);
    wpair[2] = make_float2(KWc2, KWc2); wpair[3] = make_float2(KWc3, KWc3);
    wpair[4] = make_float2(KWc4, KWc4); wpair[5] = make_float2(KWc5, KWc5);
    #define WPK(k) wpair[(k) <= 5 ? (k) : 10 - (k)]

    extern __shared__ float4 sV[];   // [TILE_Y][SVS] : (A,B,P,Q) vertical-filtered

    const int tid  = threadIdx.x;
    const int base = blockIdx.z * (IMG * IMG);
    const int x0   = blockIdx.x * TILE_X;
    const int y0   = blockIdx.y * TILE_Y;

    const bool interior = (x0 >= 5) && (x0 + EXTX - 5 <= IMG) &&
                          (y0 >= 5) && (y0 + TILE_Y + 5 <= IMG);

    // ---------------- Stage V: vertical 11-tap, f32x2 registers ------------
    {
        const int c   = tid & (EXTX - 1);
        const int g   = tid >> 6;            // row group 0..3
        const int gx  = x0 - 5 + c;
        const int iy0 = y0 + g * R - 5;

        float2 accAB[R], accPQ[R];
        #pragma unroll
        for (int o = 0; o < R; ++o) {
            accAB[o] = make_float2(0.f, 0.f);
            accPQ[o] = make_float2(0.f, 0.f);
        }

        if (interior) {
            const float* p1 = img1 + base + iy0 * IMG + gx;
            const float* p2 = img2 + base + iy0 * IMG + gx;
            #pragma unroll
            for (int j = 0; j < R + 10; ++j) {
                float a = __ldg(p1 + j * IMG);
                float b = __ldg(p2 + j * IMG);
                float2 ab = make_float2(a, b);
                float2 pq = make_float2(a * a + b * b, a * b);
                #pragma unroll
                for (int o = 0; o < R; ++o) {
                    int k = j - o;
                    if (k >= 0 && k <= 10) {
                        fma2(accAB[o], WPK(k), ab);
                        fma2(accPQ[o], WPK(k), pq);
                    }
                }
            }
        } else {
            const bool xok = (unsigned)gx < (unsigned)IMG;
            #pragma unroll
            for (int j = 0; j < R + 10; ++j) {
                int gy = iy0 + j;
                float a = 0.f, b = 0.f;
                if (xok && (unsigned)gy < (unsigned)IMG) {
                    int off = base + gy * IMG + gx;
                    a = __ldg(img1 + off);
                    b = __ldg(img2 + off);
                }
                float2 ab = make_float2(a, b);
                float2 pq = make_float2(a * a + b * b, a * b);
                #pragma unroll
                for (int o = 0; o < R; ++o) {
                    int k = j - o;
                    if (k >= 0 && k <= 10) {
                        fma2(accAB[o], WPK(k), ab);
                        fma2(accPQ[o], WPK(k), pq);
                    }
                }
            }
        }

        #pragma unroll
        for (int o = 0; o < R; ++o)
            sV[(g * R + o) * SVS + c] =
                make_float4(accAB[o].x, accAB[o].y, accPQ[o].x, accPQ[o].y);
    }
    __syncthreads();

    // ------- Stage H: j-streaming horizontal 11-tap + SSIM, 6 cols/task ----
    float loss = 0.0f;
    for (int t = tid; t < 9 * TILE_Y; t += NT) {     // 9 chunks x 48 rows = 432
        int row = t % TILE_Y;
        int c0  = (t / TILE_Y) * 6;

        float2 oAB[6], oPQ[6];
        #pragma unroll
        for (int cc = 0; cc < 6; ++cc) {
            oAB[cc] = make_float2(0.f, 0.f);
            oPQ[cc] = make_float2(0.f, 0.f);
        }

        #pragma unroll
        for (int j = 0; j < 16; ++j) {
            float4 v = sV[row * SVS + c0 + j];
            float2 vab = make_float2(v.x, v.y);
            float2 vpq = make_float2(v.z, v.w);
            #pragma unroll
            for (int cc = 0; cc < 6; ++cc) {
                int k = j - cc;
                if (k >= 0 && k <= 10) {
                    fma2(oAB[cc], WPK(k), vab);
                    fma2(oPQ[cc], WPK(k), vpq);
                }
            }
        }

        int  gy  = y0 + row;
        int  ox0 = x0 + c0;
        bool yok = gy < IMG;

        #pragma unroll
        for (int cc = 0; cc < 6; ++cc) {
            float A = oAB[cc].x, B = oAB[cc].y;
            float P = oPQ[cc].x, Q = oPQ[cc].y;
            float AB   = A * B;
            float AA   = A * A;
            float num1 = 2.0f * AB + C1V;
            float num2 = 2.0f * (Q - AB) + C2V;
            float den1 = fmaf(B, B, C1V) + AA;           // AA+BB+C1
            float den2 = (P - den1) + (C1V + C2V);       // P-AA-BB+C2
            float ssim = __fdividef(num1 * num2, den1 * den2);
            float l    = fmaf(ssim, -0.5f, 0.5f);        // (1-ssim)/2
            l = fminf(fmaxf(l, 0.0f), 0.5f);             // clip (NaN-safe)
            if (yok && (ox0 + cc) < IMG) loss += l;
        }
    }

    // ------------- Block reduction -----------------------------------------
    #pragma unroll
    for (int s = 16; s > 0; s >>= 1)
        loss += __shfl_xor_sync(0xFFFFFFFFu, loss, s);

    __shared__ float warpsum[NT / 32];
    if ((tid & 31) == 0) warpsum[tid >> 5] = loss;
    __syncthreads();

    const bool is_finisher = (blockIdx.x == GRIDX - 1) &&
                             (blockIdx.y == GRIDY - 1) &&
                             (blockIdx.z == GRIDZ - 1);   // scheduled last

    if (tid == 0) {
        float bsum = 0.f;
        #pragma unroll
        for (int w = 0; w < NT / 32; ++w) bsum += warpsum[w];

        // single packed RED: count in bits[48:64), fixed-point sum in [0:48)
        // bsum <= 1296 -> <= 2^31 units; total <= 2^43 < 2^48: no field carry
        unsigned long long pk =
            (1ull << 48) + (unsigned long long)__float2ull_rn(bsum * 1048576.0f);
        atomicAdd(&g_pack, pk);        // result unused -> REDG.64, no stall

        if (is_finisher) {
            // spin: the load that sees count==NBLK already holds the full sum
            unsigned long long v;
            do {
                v = *(volatile unsigned long long*)&g_pack;
                if ((v >> 48) != (unsigned long long)NBLK) __nanosleep(64);
            } while ((v >> 48) != (unsigned long long)NBLK);

            double total = (double)(v & 0xFFFFFFFFFFFFull) * (1.0 / 1048576.0);
            const double inv_total = 1.0 / (16.0 * 3.0 * 512.0 * 512.0);
            out[0] = (float)(total * inv_total);

            g_pack = 0ull;             // reset for next graph replay
        }
    }
}

extern "C" void kernel_launch(void* const* d_in, const int* in_sizes, int n_in,
                              void* d_out, int out_size)
{
    const float* img1 = (const float*)d_in[0];
    const float* img2 = (const float*)d_in[1];
    float* out = (float*)d_out;

    const int smem_bytes = TILE_Y * SVS * (int)sizeof(float4);  // 49920
    cudaFuncSetAttribute(ssim_pack_kernel,
                         cudaFuncAttributeMaxDynamicSharedMemorySize, smem_bytes);

    dim3 grid(GRIDX, GRIDY, GRIDZ);   // 10 x 11 x 48 = 5280 blocks
    ssim_pack_kernel<<<grid, NT, smem_bytes>>>(img1, img2, out);
}

// round 17
// speedup vs baseline: 1.0707x; 1.0016x over previous
#include <cuda_runtime.h>

// SSIM loss — R8 compute structure (TILE_Y=32, 4 CTAs/SM, perfect 256-task
// stage H) + R16 packed single-word RED finisher (zero ordering ops,
// fixed-point deterministic). R8's original 60.8us carried a ~4.8us
// fence+ATOMG tail (calibrated R11 vs R16); this removes it.

#define NT      256
#define EXTX    64
#define TILE_X  54
#define TILE_Y  32
#define R       8
#define SVS     65          // row stride in 16B elements (odd -> conflict-free)
#define IMG     512
#define GRIDX   10
#define GRIDY   16
#define GRIDZ   48
#define NBLK    (GRIDX * GRIDY * GRIDZ)

#define KWc0 0.0010283801f
#define KWc1 0.0075987582f
#define KWc2 0.0360007696f
#define KWc3 0.1093606947f
#define KWc4 0.2130055430f
#define KWc5 0.2660117300f

#define C1V 0.0001f
#define C2V 0.0009f

__device__ unsigned long long g_pack = 0ull;

__device__ __forceinline__ void fma2(float2& d, float2 a, float2 b) {
    asm("fma.rn.f32x2 %0, %1, %2, %0;"
        : "+l"(reinterpret_cast<unsigned long long&>(d))
        : "l"(reinterpret_cast<const unsigned long long&>(a)),
          "l"(reinterpret_cast<const unsigned long long&>(b)));
}

__global__ void __launch_bounds__(NT, 4)
ssim_t32p_kernel(const float* __restrict__ img1,
                 const float* __restrict__ img2,
                 float* __restrict__ out)
{
    float2 wpair[6];
    wpair[0] = make_float2(KWc0, KWc0); wpair[1] = make_float2(KWc1, KWc1);
    wpair[2] = make_float2(KWc2, KWc2); wpair[3] = make_float2(KWc3, KWc3);
    wpair[4] = make_float2(KWc4, KWc4); wpair[5] = make_float2(KWc5, KWc5);
    #define WPK(k) wpair[(k) <= 5 ? (k) : 10 - (k)]

    extern __shared__ float4 sV[];   // [TILE_Y][SVS]+pad : (A,B,P,Q)

    const int tid  = threadIdx.x;
    const int base = blockIdx.z * (IMG * IMG);
    const int x0   = blockIdx.x * TILE_X;
    const int y0   = blockIdx.y * TILE_Y;

    const bool interior = (x0 >= 5) && (x0 + EXTX - 5 <= IMG) &&
                          (y0 >= 5) && (y0 + TILE_Y + 5 <= IMG);

    // zero the 2 pad elements read by the widest H window (cols 64,65 of
    // the last chunk feed only masked outputs, but keep them finite)
    if (tid < 2) sV[TILE_Y * SVS + tid] = make_float4(0.f, 0.f, 0.f, 0.f);

    // ---------------- Stage V: vertical 11-tap, f32x2 registers ------------
    {
        const int c   = tid & (EXTX - 1);
        const int g   = tid >> 6;            // row group 0..3 (R rows each)
        const int gx  = x0 - 5 + c;
        const int iy0 = y0 + g * R - 5;

        float2 accAB[R], accPQ[R];
        #pragma unroll
        for (int o = 0; o < R; ++o) {
            accAB[o] = make_float2(0.f, 0.f);
            accPQ[o] = make_float2(0.f, 0.f);
        }

        if (interior) {
            const float* p1 = img1 + base + iy0 * IMG + gx;
            const float* p2 = img2 + base + iy0 * IMG + gx;
            #pragma unroll
            for (int j = 0; j < R + 10; ++j) {
                float a = __ldg(p1 + j * IMG);
                float b = __ldg(p2 + j * IMG);
                float2 ab = make_float2(a, b);
                float2 pq = make_float2(a * a + b * b, a * b);
                #pragma unroll
                for (int o = 0; o < R; ++o) {
                    int k = j - o;
                    if (k >= 0 && k <= 10) {
                        fma2(accAB[o], WPK(k), ab);
                        fma2(accPQ[o], WPK(k), pq);
                    }
                }
            }
        } else {
            const bool xok = (unsigned)gx < (unsigned)IMG;
            #pragma unroll
            for (int j = 0; j < R + 10; ++j) {
                int gy = iy0 + j;
                float a = 0.f, b = 0.f;
                if (xok && (unsigned)gy < (unsigned)IMG) {
                    int off = base + gy * IMG + gx;
                    a = __ldg(img1 + off);
                    b = __ldg(img2 + off);
                }
                float2 ab = make_float2(a, b);
                float2 pq = make_float2(a * a + b * b, a * b);
                #pragma unroll
                for (int o = 0; o < R; ++o) {
                    int k = j - o;
                    if (k >= 0 && k <= 10) {
                        fma2(accAB[o], WPK(k), ab);
                        fma2(accPQ[o], WPK(k), pq);
                    }
                }
            }
        }

        #pragma unroll
        for (int o = 0; o < R; ++o)
            sV[(g * R + o) * SVS + c] =
                make_float4(accAB[o].x, accAB[o].y, accPQ[o].x, accPQ[o].y);
    }
    __syncthreads();

    // ------- Stage H: 11-tap + SSIM; 8 chunks x 7 outputs, 256 tasks -------
    float loss = 0.0f;
    {
        const int row = tid & (TILE_Y - 1);      // 0..31
        const int c0  = (tid >> 5) * 7;          // 0,7,...,49

        float2 oAB[7], oPQ[7];
        #pragma unroll
        for (int cc = 0; cc < 7; ++cc) {
            oAB[cc] = make_float2(0.f, 0.f);
            oPQ[cc] = make_float2(0.f, 0.f);
        }

        #pragma unroll
        for (int j = 0; j < 17; ++j) {
            float4 v = sV[row * SVS + c0 + j];   // cols 64,65 = zero pad
            float2 vab = make_float2(v.x, v.y);
            float2 vpq = make_float2(v.z, v.w);
            #pragma unroll
            for (int cc = 0; cc < 7; ++cc) {
                int k = j - cc;
                if (k >= 0 && k <= 10) {
                    fma2(oAB[cc], WPK(k), vab);
                    fma2(oPQ[cc], WPK(k), vpq);
                }
            }
        }

        const int ox0 = x0 + c0;
        #pragma unroll
        for (int cc = 0; cc < 7; ++cc) {
            float A = oAB[cc].x, B = oAB[cc].y;
            float P = oPQ[cc].x, Q = oPQ[cc].y;
            float AB   = A * B;
            float AA   = A * A;
            float num1 = 2.0f * AB + C1V;
            float num2 = 2.0f * (Q - AB) + C2V;
            float den1 = fmaf(B, B, C1V) + AA;           // AA+BB+C1
            float den2 = (P - den1) + (C1V + C2V);       // P-AA-BB+C2
            float ssim = __fdividef(num1 * num2, den1 * den2);
            float l    = fmaf(ssim, -0.5f, 0.5f);        // (1-ssim)/2
            l = fminf(fmaxf(l, 0.0f), 0.5f);             // clip (NaN-safe)
            if ((c0 + cc) < TILE_X && (ox0 + cc) < IMG) loss += l;
        }
    }

    // ------------- Block reduction -----------------------------------------
    #pragma unroll
    for (int s = 16; s > 0; s >>= 1)
        loss += __shfl_xor_sync(0xFFFFFFFFu, loss, s);

    __shared__ float warpsum[NT / 32];
    if ((tid & 31) == 0) warpsum[tid >> 5] = loss;
    __syncthreads();

    const bool is_finisher = (blockIdx.x == GRIDX - 1) &&
                             (blockIdx.y == GRIDY - 1) &&
                             (blockIdx.z == GRIDZ - 1);   // scheduled last

    if (tid == 0) {
        float bsum = 0.f;
        #pragma unroll
        for (int w = 0; w < NT / 32; ++w) bsum += warpsum[w];

        // single packed RED: count in bits[48:64), fixed-point sum in [0:48)
        // bsum <= 864 -> < 2^31 units; total < 2^43 < 2^48: no field carry
        unsigned long long pk =
            (1ull << 48) + (unsigned long long)__float2ull_rn(bsum * 1048576.0f);
        atomicAdd(&g_pack, pk);        // result unused -> REDG.64, no stall

        if (is_finisher) {
            // spin: the load that sees count==NBLK already holds the full sum
            unsigned long long v;
            do {
                v = *(volatile unsigned long long*)&g_pack;
                if ((v >> 48) != (unsigned long long)NBLK) __nanosleep(64);
            } while ((v >> 48) != (unsigned long long)NBLK);

            double total = (double)(v & 0xFFFFFFFFFFFFull) * (1.0 / 1048576.0);
            const double inv_total = 1.0 / (16.0 * 3.0 * 512.0 * 512.0);
            out[0] = (float)(total * inv_total);

            g_pack = 0ull;             // reset for next graph replay
        }
    }
}

extern "C" void kernel_launch(void* const* d_in, const int* in_sizes, int n_in,
                              void* d_out, int out_size)
{
    const float* img1 = (const float*)d_in[0];
    const float* img2 = (const float*)d_in[1];
    float* out = (float*)d_out;

    // +2 pad elements: widest H window (row 31, cols 64-65) stays in bounds
    const int smem_bytes = (TILE_Y * SVS + 2) * (int)sizeof(float4);  // 33312
    cudaFuncSetAttribute(ssim_t32p_kernel,
                         cudaFuncAttributeMaxDynamicSharedMemorySize, smem_bytes);

    dim3 grid(GRIDX, GRIDY, GRIDZ);   // 10 x 16 x 48 = 7680 blocks
    ssim_t32p_kernel<<<grid, NT, smem_bytes>>>(img1, img2, out);
}